// round 1
// baseline (speedup 1.0000x reference)
#include <cuda_runtime.h>
#include <cstdint>
#include <cstddef>

// ---------------------------------------------------------------------------
// Problem constants
// ---------------------------------------------------------------------------
#define BDIM 1024
#define SDIM 64
#define DDIM 768
#define POOLN 30
#define TOPK 4
#define SEQL 68          // TOPK + SDIM
#define CTOK 64

#define OFF_RSIM (BDIM*CTOK*DDIM)               // 50331648
#define OFF_SIM  (OFF_RSIM + 1)                 // 50331649
#define OFF_IDX  (OFF_SIM + BDIM*POOLN)         // 50362369
#define OUT_TOTAL (OFF_IDX + BDIM*TOPK)         // 50366465

// ---------------------------------------------------------------------------
// Scratch (static __device__ arrays — no allocation at runtime)
// ---------------------------------------------------------------------------
__device__ float g_pnorm[POOLN * DDIM];
__device__ float g_xnorm[BDIM * DDIM];
__device__ int   g_idx[BDIM * TOPK];
__device__ float g_rsum[BDIM];
__device__ float g_bufA[(size_t)BDIM * CTOK * DDIM];  // z_t, then u
__device__ float g_bufB[(size_t)BDIM * CTOK * DDIM];  // pre-LN GEMM outputs

// ---------------------------------------------------------------------------
// K1: prompt_norm = l2_normalize(prompt, axis=1).  grid=30, block=256
// ---------------------------------------------------------------------------
__global__ __launch_bounds__(256) void pnorm_kernel(const float* __restrict__ prompt) {
    int p = blockIdx.x;
    int tid = threadIdx.x;
    const float* row = prompt + (size_t)p * DDIM;
    float v0 = row[tid], v1 = row[tid + 256], v2 = row[tid + 512];
    float ssq = v0 * v0 + v1 * v1 + v2 * v2;
    __shared__ float sh[8];
    #pragma unroll
    for (int o = 16; o; o >>= 1) ssq += __shfl_down_sync(0xffffffffu, ssq, o);
    if ((tid & 31) == 0) sh[tid >> 5] = ssq;
    __syncthreads();
    if (tid < 32) {
        float v = (tid < 8) ? sh[tid] : 0.f;
        #pragma unroll
        for (int o = 4; o; o >>= 1) v += __shfl_down_sync(0xffffffffu, v, o);
        if (tid == 0) sh[0] = v;
    }
    __syncthreads();
    float rn = rsqrtf(fmaxf(sh[0], 1e-12f));
    float* dst = g_pnorm + (size_t)p * DDIM;
    dst[tid]       = v0 * rn;
    dst[tid + 256] = v1 * rn;
    dst[tid + 512] = v2 * rn;
}

// ---------------------------------------------------------------------------
// K2: x_mean over S, then l2_normalize -> g_xnorm.  grid=B, block=256
// ---------------------------------------------------------------------------
__global__ __launch_bounds__(256) void xmean_norm_kernel(const float* __restrict__ x) {
    int b = blockIdx.x;
    int tid = threadIdx.x;
    float m[3];
    float ssq = 0.f;
    #pragma unroll
    for (int i = 0; i < 3; i++) {
        int d = tid + i * 256;
        float s = 0.f;
        #pragma unroll 8
        for (int si = 0; si < SDIM; si++)
            s += x[((size_t)b * SDIM + si) * DDIM + d];
        m[i] = s * (1.f / SDIM);
        ssq += m[i] * m[i];
    }
    __shared__ float sh[8];
    #pragma unroll
    for (int o = 16; o; o >>= 1) ssq += __shfl_down_sync(0xffffffffu, ssq, o);
    if ((tid & 31) == 0) sh[tid >> 5] = ssq;
    __syncthreads();
    if (tid < 32) {
        float v = (tid < 8) ? sh[tid] : 0.f;
        #pragma unroll
        for (int o = 4; o; o >>= 1) v += __shfl_down_sync(0xffffffffu, v, o);
        if (tid == 0) sh[0] = v;
    }
    __syncthreads();
    float rn = rsqrtf(fmaxf(sh[0], 1e-12f));
    #pragma unroll
    for (int i = 0; i < 3; i++)
        g_xnorm[(size_t)b * DDIM + tid + i * 256] = m[i] * rn;
}

// ---------------------------------------------------------------------------
// K3: similarity (B,30), top-4 indices, per-batch reduce_sim partial.
// grid=B, block=256.  sim[b,p] = x_norm[b] . prompt_norm[p]
// Note selected_key[j].x_norm == similarity[b, idx[b,j]], so reduce_sim is
// just the sum of the top-4 similarities.
// ---------------------------------------------------------------------------
__global__ __launch_bounds__(256) void sim_topk_kernel(float* __restrict__ out, int write_aux) {
    int b = blockIdx.x;
    int tid = threadIdx.x;
    __shared__ float sx[DDIM];
    __shared__ float ssim[32];
    for (int i = tid; i < DDIM; i += 256) sx[i] = g_xnorm[(size_t)b * DDIM + i];
    __syncthreads();
    int p = tid >> 3;         // 0..31 (30 used)
    int l8 = tid & 7;
    float acc = 0.f;
    if (p < POOLN) {
        const float* pr = g_pnorm + (size_t)p * DDIM;
        for (int k = l8; k < DDIM; k += 8) acc += sx[k] * pr[k];
    }
    #pragma unroll
    for (int o = 4; o; o >>= 1) acc += __shfl_down_sync(0xffffffffu, acc, o, 8);
    if (l8 == 0 && p < POOLN) ssim[p] = acc;
    __syncthreads();
    if (write_aux && tid < POOLN) out[OFF_SIM + (size_t)b * POOLN + tid] = ssim[tid];
    if (tid == 0) {
        bool used[POOLN];
        #pragma unroll
        for (int i = 0; i < POOLN; i++) used[i] = false;
        float rs = 0.f;
        for (int k = 0; k < TOPK; k++) {
            int best = 0;
            float bv = -3.4e38f;
            for (int pp = 0; pp < POOLN; pp++) {
                if (!used[pp] && ssim[pp] > bv) { bv = ssim[pp]; best = pp; }
            }
            used[best] = true;
            g_idx[b * TOPK + k] = best;
            if (write_aux) out[OFF_IDX + (size_t)b * TOPK + k] = (float)best;
            rs += bv;
        }
        g_rsum[b] = rs;
    }
}

// ---------------------------------------------------------------------------
// K3b: deterministic reduction of g_rsum -> out[OFF_RSIM].  1 block, 256 thr.
// ---------------------------------------------------------------------------
__global__ __launch_bounds__(256) void reduce_rsim_kernel(float* __restrict__ out) {
    int tid = threadIdx.x;
    float v = g_rsum[tid] + g_rsum[tid + 256] + g_rsum[tid + 512] + g_rsum[tid + 768];
    __shared__ float sh[8];
    #pragma unroll
    for (int o = 16; o; o >>= 1) v += __shfl_down_sync(0xffffffffu, v, o);
    if ((tid & 31) == 0) sh[tid >> 5] = v;
    __syncthreads();
    if (tid < 32) {
        float w = (tid < 8) ? sh[tid] : 0.f;
        #pragma unroll
        for (int o = 4; o; o >>= 1) w += __shfl_down_sync(0xffffffffu, w, o);
        if (tid == 0) out[OFF_RSIM] = w * (1.f / BDIM);
    }
}

// ---------------------------------------------------------------------------
// K4: fully fused mlp_1 (token mixing).  grid = (12 d-chunks, B), block=256.
// Per block: gather A[s][d'] (68 x 64) from prompt[idx] ++ x_embed,
//   h1 = LN_c(relu(A^T @ w1a + b1a))        (64d x 64c)
//   h2 = LN_c(relu(h1 @ w1b + b1b))
//   write transposed: g_bufA[(b*64+c)*768 + d0+d'] = h2[d'][c]
// Dynamic smem: 17088 floats (68352 B).
// ---------------------------------------------------------------------------
__global__ __launch_bounds__(256) void mlp1_fused_kernel(
    const float* __restrict__ x_embed, const float* __restrict__ prompt,
    const float* __restrict__ w1a, const float* __restrict__ b1a,
    const float* __restrict__ g1a, const float* __restrict__ be1a,
    const float* __restrict__ w1b, const float* __restrict__ b1b,
    const float* __restrict__ g1b, const float* __restrict__ be1b)
{
    extern __shared__ float sm[];
    float* sW1a  = sm;              // 68*64 = 4352
    float* sW1b  = sm + 4352;       // 64*64 = 4096
    float* sA    = sm + 8448;       // 68*64 = 4352  (later reused as H2, stride 65)
    float* sH    = sm + 12800;      // 64*65 = 4160
    float* sMean = sm + 16960;      // 64
    float* sRstd = sm + 17024;      // 64  -> total 17088 floats

    int b  = blockIdx.y;
    int d0 = blockIdx.x * 64;
    int tid = threadIdx.x;

    for (int i = tid; i < SEQL * 64; i += 256) sW1a[i] = w1a[i];
    for (int i = tid; i < 64 * 64;  i += 256) sW1b[i] = w1b[i];
    for (int i = tid; i < SEQL * 64; i += 256) {
        int s = i >> 6, dd = i & 63;
        float v;
        if (s < TOPK)
            v = prompt[(size_t)g_idx[b * TOPK + s] * DDIM + d0 + dd];
        else
            v = x_embed[((size_t)b * SDIM + (s - TOPK)) * DDIM + d0 + dd];
        sA[i] = v;
    }
    __syncthreads();

    int tx = tid & 15;   // c-group
    int ty = tid >> 4;   // d-group
    float acc[4][4];
    #pragma unroll
    for (int i = 0; i < 4; i++)
        #pragma unroll
        for (int j = 0; j < 4; j++) acc[i][j] = 0.f;

    // GEMM1: h1[d][c] = sum_s A[s][d] * w1a[s][c]
    #pragma unroll 4
    for (int s = 0; s < SEQL; s++) {
        float a[4], w[4];
        #pragma unroll
        for (int i = 0; i < 4; i++) a[i] = sA[s * 64 + ty * 4 + i];
        #pragma unroll
        for (int j = 0; j < 4; j++) w[j] = sW1a[s * 64 + tx * 4 + j];
        #pragma unroll
        for (int i = 0; i < 4; i++)
            #pragma unroll
            for (int j = 0; j < 4; j++) acc[i][j] += a[i] * w[j];
    }
    // bias + relu -> sH (stride 65)
    #pragma unroll
    for (int i = 0; i < 4; i++) {
        int r = ty * 4 + i;
        #pragma unroll
        for (int j = 0; j < 4; j++) {
            int c = tx * 4 + j;
            sH[r * 65 + c] = fmaxf(acc[i][j] + b1a[c], 0.f);
        }
    }
    __syncthreads();
    // LN over c (per d-row)
    if (tid < 64) {
        float s = 0.f, sq = 0.f;
        #pragma unroll 8
        for (int c = 0; c < 64; c++) { float v = sH[tid * 65 + c]; s += v; sq += v * v; }
        float m = s * (1.f / 64.f);
        float var = sq * (1.f / 64.f) - m * m;
        sMean[tid] = m;
        sRstd[tid] = rsqrtf(fmaxf(var, 0.f) + 1e-5f);
    }
    __syncthreads();
    for (int i = tid; i < 4096; i += 256) {
        int r = i >> 6, c = i & 63;
        sH[r * 65 + c] = (sH[r * 65 + c] - sMean[r]) * sRstd[r] * g1a[c] + be1a[c];
    }
    __syncthreads();

    // GEMM2: h2[d][c] = sum_k h1[d][k] * w1b[k][c]
    #pragma unroll
    for (int i = 0; i < 4; i++)
        #pragma unroll
        for (int j = 0; j < 4; j++) acc[i][j] = 0.f;
    #pragma unroll 8
    for (int k = 0; k < 64; k++) {
        float a[4], w[4];
        #pragma unroll
        for (int i = 0; i < 4; i++) a[i] = sH[(ty * 4 + i) * 65 + k];
        #pragma unroll
        for (int j = 0; j < 4; j++) w[j] = sW1b[k * 64 + tx * 4 + j];
        #pragma unroll
        for (int i = 0; i < 4; i++)
            #pragma unroll
            for (int j = 0; j < 4; j++) acc[i][j] += a[i] * w[j];
    }
    // bias + relu -> H2 (reuse sA, stride 65; 4160 <= 4352)
    #pragma unroll
    for (int i = 0; i < 4; i++) {
        int r = ty * 4 + i;
        #pragma unroll
        for (int j = 0; j < 4; j++) {
            int c = tx * 4 + j;
            sA[r * 65 + c] = fmaxf(acc[i][j] + b1b[c], 0.f);
        }
    }
    __syncthreads();
    if (tid < 64) {
        float s = 0.f, sq = 0.f;
        #pragma unroll 8
        for (int c = 0; c < 64; c++) { float v = sA[tid * 65 + c]; s += v; sq += v * v; }
        float m = s * (1.f / 64.f);
        float var = sq * (1.f / 64.f) - m * m;
        sMean[tid] = m;
        sRstd[tid] = rsqrtf(fmaxf(var, 0.f) + 1e-5f);
    }
    __syncthreads();
    for (int i = tid; i < 4096; i += 256) {
        int r = i >> 6, c = i & 63;
        sA[r * 65 + c] = (sA[r * 65 + c] - sMean[r]) * sRstd[r] * g1b[c] + be1b[c];
    }
    __syncthreads();
    // transposed write: z_t[(b*64 + c)*768 + d0 + dd] = h2[dd][c]
    for (int i = tid; i < 4096; i += 256) {
        int c = i >> 6, dd = i & 63;
        g_bufA[((size_t)b * CTOK + c) * DDIM + d0 + dd] = sA[dd * 65 + c];
    }
}

// ---------------------------------------------------------------------------
// K5/K7: SGEMM  C = relu(A @ W + bias).  A: MxK row-major, W: KxN row-major.
// BM=128 BN=128 BK=8, TM=TN=8, 256 threads. M,N,K all divisible -> no guards.
// ---------------------------------------------------------------------------
#define GBM 128
#define GBN 128
#define GBK 8
#define GTM 8
#define GTN 8

__global__ __launch_bounds__(256) void gemm_bias_relu_kernel(
    const float* __restrict__ A, const float* __restrict__ W,
    const float* __restrict__ bias, float* __restrict__ C,
    int M, int N, int K)
{
    __shared__ float As[GBK * GBM];
    __shared__ float Bs[GBK * GBN];

    int bx = blockIdx.x;  // N tile
    int by = blockIdx.y;  // M tile
    int tid = threadIdx.x;

    int threadCol = tid % (GBN / GTN);   // 0..15
    int threadRow = tid / (GBN / GTN);   // 0..15

    const float* Aptr = A + (size_t)by * GBM * K;
    const float* Wptr = W + (size_t)bx * GBN;

    int innerRowA = tid >> 1;            // 0..127
    int innerColA = (tid & 1) * 4;       // 0 or 4
    int innerRowB = tid >> 5;            // 0..7
    int innerColB = (tid & 31) * 4;      // 0..124

    float acc[GTM][GTN];
    #pragma unroll
    for (int i = 0; i < GTM; i++)
        #pragma unroll
        for (int j = 0; j < GTN; j++) acc[i][j] = 0.f;

    for (int k0 = 0; k0 < K; k0 += GBK) {
        float4 av = *(const float4*)(Aptr + (size_t)innerRowA * K + k0 + innerColA);
        As[(innerColA + 0) * GBM + innerRowA] = av.x;
        As[(innerColA + 1) * GBM + innerRowA] = av.y;
        As[(innerColA + 2) * GBM + innerRowA] = av.z;
        As[(innerColA + 3) * GBM + innerRowA] = av.w;
        *(float4*)(&Bs[innerRowB * GBN + innerColB]) =
            *(const float4*)(Wptr + (size_t)(k0 + innerRowB) * N + innerColB);
        __syncthreads();

        #pragma unroll
        for (int k = 0; k < GBK; k++) {
            float regM[GTM], regN[GTN];
            #pragma unroll
            for (int i = 0; i < GTM; i++) regM[i] = As[k * GBM + threadRow * GTM + i];
            #pragma unroll
            for (int j = 0; j < GTN; j++) regN[j] = Bs[k * GBN + threadCol * GTN + j];
            #pragma unroll
            for (int i = 0; i < GTM; i++)
                #pragma unroll
                for (int j = 0; j < GTN; j++) acc[i][j] += regM[i] * regN[j];
        }
        __syncthreads();
    }

    int colBase = bx * GBN + threadCol * GTN;
    #pragma unroll
    for (int i = 0; i < GTM; i++) {
        size_t row = (size_t)by * GBM + threadRow * GTM + i;
        #pragma unroll
        for (int j = 0; j < GTN; j += 4) {
            float4 v;
            v.x = fmaxf(acc[i][j + 0] + bias[colBase + j + 0], 0.f);
            v.y = fmaxf(acc[i][j + 1] + bias[colBase + j + 1], 0.f);
            v.z = fmaxf(acc[i][j + 2] + bias[colBase + j + 2], 0.f);
            v.w = fmaxf(acc[i][j + 3] + bias[colBase + j + 3], 0.f);
            *(float4*)(&C[row * N + colBase + j]) = v;
        }
    }
}

// ---------------------------------------------------------------------------
// K6/K8: per-row LayerNorm over 768.  grid = B*CT rows, block=256.
// ---------------------------------------------------------------------------
__global__ __launch_bounds__(256) void ln_rows_kernel(
    const float* __restrict__ in, float* __restrict__ out,
    const float* __restrict__ g, const float* __restrict__ be)
{
    size_t row = blockIdx.x;
    int tid = threadIdx.x;
    const float* p = in + row * DDIM;
    float* q = out + row * DDIM;
    float v0 = p[tid], v1 = p[tid + 256], v2 = p[tid + 512];
    float s = v0 + v1 + v2;
    float sq = v0 * v0 + v1 * v1 + v2 * v2;
    __shared__ float sh[16];
    #pragma unroll
    for (int o = 16; o; o >>= 1) {
        s  += __shfl_down_sync(0xffffffffu, s, o);
        sq += __shfl_down_sync(0xffffffffu, sq, o);
    }
    if ((tid & 31) == 0) { sh[tid >> 5] = s; sh[8 + (tid >> 5)] = sq; }
    __syncthreads();
    if (tid < 32) {
        float a = (tid < 8) ? sh[tid] : 0.f;
        float c = (tid < 8) ? sh[8 + tid] : 0.f;
        #pragma unroll
        for (int o = 4; o; o >>= 1) {
            a += __shfl_down_sync(0xffffffffu, a, o);
            c += __shfl_down_sync(0xffffffffu, c, o);
        }
        if (tid == 0) { sh[0] = a; sh[1] = c; }
    }
    __syncthreads();
    float mean = sh[0] * (1.f / DDIM);
    float var  = sh[1] * (1.f / DDIM) - mean * mean;
    float rstd = rsqrtf(fmaxf(var, 0.f) + 1e-5f);
    q[tid]       = (v0 - mean) * rstd * g[tid]       + be[tid];
    q[tid + 256] = (v1 - mean) * rstd * g[tid + 256] + be[tid + 256];
    q[tid + 512] = (v2 - mean) * rstd * g[tid + 512] + be[tid + 512];
}

// ---------------------------------------------------------------------------
// Launch
// ---------------------------------------------------------------------------
extern "C" void kernel_launch(void* const* d_in, const int* in_sizes, int n_in,
                              void* d_out, int out_size)
{
    const float* x_embed = (const float*)d_in[0];
    const float* prompt  = (const float*)d_in[1];
    const float* w1a  = (const float*)d_in[2];
    const float* b1a  = (const float*)d_in[3];
    const float* g1a  = (const float*)d_in[4];
    const float* be1a = (const float*)d_in[5];
    const float* w1b  = (const float*)d_in[6];
    const float* b1b  = (const float*)d_in[7];
    const float* g1b  = (const float*)d_in[8];
    const float* be1b = (const float*)d_in[9];
    const float* w2a  = (const float*)d_in[10];
    const float* b2a  = (const float*)d_in[11];
    const float* g2a  = (const float*)d_in[12];
    const float* be2a = (const float*)d_in[13];
    const float* w2b  = (const float*)d_in[14];
    const float* b2b  = (const float*)d_in[15];
    const float* g2b  = (const float*)d_in[16];
    const float* be2b = (const float*)d_in[17];
    float* out = (float*)d_out;

    int write_aux = (out_size >= OUT_TOTAL) ? 1 : 0;

    float *bufA = nullptr, *bufB = nullptr;
    cudaGetSymbolAddress((void**)&bufA, g_bufA);
    cudaGetSymbolAddress((void**)&bufB, g_bufB);

    // prompt selection pipeline
    pnorm_kernel<<<POOLN, 256>>>(prompt);
    xmean_norm_kernel<<<BDIM, 256>>>(x_embed);
    sim_topk_kernel<<<BDIM, 256>>>(out, write_aux);
    if (write_aux) reduce_rsim_kernel<<<1, 256>>>(out);

    // fused mlp_1 (token mixing): writes z_t into bufA
    int mlp1_smem = 17088 * (int)sizeof(float);
    cudaFuncSetAttribute(mlp1_fused_kernel,
                         cudaFuncAttributeMaxDynamicSharedMemorySize, mlp1_smem);
    mlp1_fused_kernel<<<dim3(DDIM / 64, BDIM), 256, mlp1_smem>>>(
        x_embed, prompt, w1a, b1a, g1a, be1a, w1b, b1b, g1b, be1b);

    // mlp_2 (channel mixing): two GEMM + LN stages
    dim3 ggrid(DDIM / GBN, (BDIM * CTOK) / GBM);   // (6, 512)
    gemm_bias_relu_kernel<<<ggrid, 256>>>(bufA, w2a, b2a, bufB,
                                          BDIM * CTOK, DDIM, DDIM);
    ln_rows_kernel<<<BDIM * CTOK, 256>>>(bufB, bufA, g2a, be2a);
    gemm_bias_relu_kernel<<<ggrid, 256>>>(bufA, w2b, b2b, bufB,
                                          BDIM * CTOK, DDIM, DDIM);
    ln_rows_kernel<<<BDIM * CTOK, 256>>>(bufB, out, g2b, be2b);
}

// round 2
// speedup vs baseline: 1.9746x; 1.9746x over previous
#include <cuda_runtime.h>
#include <cstdint>
#include <cstddef>

// ---------------------------------------------------------------------------
// Problem constants
// ---------------------------------------------------------------------------
#define BDIM 1024
#define SDIM 64
#define DDIM 768
#define POOLN 30
#define TOPK 4
#define SEQL 68          // TOPK + SDIM
#define CTOK 64

#define OFF_RSIM (BDIM*CTOK*DDIM)               // 50331648
#define OFF_SIM  (OFF_RSIM + 1)                 // 50331649
#define OFF_IDX  (OFF_SIM + BDIM*POOLN)         // 50362369
#define OUT_TOTAL (OFF_IDX + BDIM*TOPK)         // 50366465

// ---------------------------------------------------------------------------
// Scratch (static __device__ arrays — no allocation at runtime)
// ---------------------------------------------------------------------------
__device__ float g_pnorm[POOLN * DDIM];
__device__ float g_xnorm[BDIM * DDIM];
__device__ int   g_idx[BDIM * TOPK];
__device__ float g_rsum[BDIM];
__device__ float g_bufA[(size_t)BDIM * CTOK * DDIM];  // z_t, then u
__device__ float g_bufB[(size_t)BDIM * CTOK * DDIM];  // pre-LN GEMM outputs

// ---------------------------------------------------------------------------
// tf32 helpers
// ---------------------------------------------------------------------------
__device__ __forceinline__ uint32_t f2tf32(float f) {
    uint32_t u;
    asm("cvt.rna.tf32.f32 %0, %1;" : "=r"(u) : "f"(f));
    return u;
}

__device__ __forceinline__ void mma_tf32(float c[4],
    uint32_t a0, uint32_t a1, uint32_t a2, uint32_t a3,
    uint32_t b0, uint32_t b1)
{
    asm volatile(
        "mma.sync.aligned.m16n8k8.row.col.f32.tf32.tf32.f32 "
        "{%0,%1,%2,%3}, {%4,%5,%6,%7}, {%8,%9}, {%0,%1,%2,%3};"
        : "+f"(c[0]), "+f"(c[1]), "+f"(c[2]), "+f"(c[3])
        : "r"(a0), "r"(a1), "r"(a2), "r"(a3), "r"(b0), "r"(b1));
}

// ---------------------------------------------------------------------------
// K1: prompt_norm = l2_normalize(prompt, axis=1).  grid=30, block=256
// ---------------------------------------------------------------------------
__global__ __launch_bounds__(256) void pnorm_kernel(const float* __restrict__ prompt) {
    int p = blockIdx.x;
    int tid = threadIdx.x;
    const float* row = prompt + (size_t)p * DDIM;
    float v0 = row[tid], v1 = row[tid + 256], v2 = row[tid + 512];
    float ssq = v0 * v0 + v1 * v1 + v2 * v2;
    __shared__ float sh[8];
    #pragma unroll
    for (int o = 16; o; o >>= 1) ssq += __shfl_down_sync(0xffffffffu, ssq, o);
    if ((tid & 31) == 0) sh[tid >> 5] = ssq;
    __syncthreads();
    if (tid < 32) {
        float v = (tid < 8) ? sh[tid] : 0.f;
        #pragma unroll
        for (int o = 4; o; o >>= 1) v += __shfl_down_sync(0xffffffffu, v, o);
        if (tid == 0) sh[0] = v;
    }
    __syncthreads();
    float rn = rsqrtf(fmaxf(sh[0], 1e-12f));
    float* dst = g_pnorm + (size_t)p * DDIM;
    dst[tid]       = v0 * rn;
    dst[tid + 256] = v1 * rn;
    dst[tid + 512] = v2 * rn;
}

// ---------------------------------------------------------------------------
// K2: x_mean over S, then l2_normalize -> g_xnorm.  grid=B, block=256
// ---------------------------------------------------------------------------
__global__ __launch_bounds__(256) void xmean_norm_kernel(const float* __restrict__ x) {
    int b = blockIdx.x;
    int tid = threadIdx.x;
    float m[3];
    float ssq = 0.f;
    #pragma unroll
    for (int i = 0; i < 3; i++) {
        int d = tid + i * 256;
        float s = 0.f;
        #pragma unroll 8
        for (int si = 0; si < SDIM; si++)
            s += x[((size_t)b * SDIM + si) * DDIM + d];
        m[i] = s * (1.f / SDIM);
        ssq += m[i] * m[i];
    }
    __shared__ float sh[8];
    #pragma unroll
    for (int o = 16; o; o >>= 1) ssq += __shfl_down_sync(0xffffffffu, ssq, o);
    if ((tid & 31) == 0) sh[tid >> 5] = ssq;
    __syncthreads();
    if (tid < 32) {
        float v = (tid < 8) ? sh[tid] : 0.f;
        #pragma unroll
        for (int o = 4; o; o >>= 1) v += __shfl_down_sync(0xffffffffu, v, o);
        if (tid == 0) sh[0] = v;
    }
    __syncthreads();
    float rn = rsqrtf(fmaxf(sh[0], 1e-12f));
    #pragma unroll
    for (int i = 0; i < 3; i++)
        g_xnorm[(size_t)b * DDIM + tid + i * 256] = m[i] * rn;
}

// ---------------------------------------------------------------------------
// K3: similarity (B,30), top-4 indices, per-batch reduce_sim partial.
// ---------------------------------------------------------------------------
__global__ __launch_bounds__(256) void sim_topk_kernel(float* __restrict__ out, int write_aux) {
    int b = blockIdx.x;
    int tid = threadIdx.x;
    __shared__ float sx[DDIM];
    __shared__ float ssim[32];
    for (int i = tid; i < DDIM; i += 256) sx[i] = g_xnorm[(size_t)b * DDIM + i];
    __syncthreads();
    int p = tid >> 3;
    int l8 = tid & 7;
    float acc = 0.f;
    if (p < POOLN) {
        const float* pr = g_pnorm + (size_t)p * DDIM;
        for (int k = l8; k < DDIM; k += 8) acc += sx[k] * pr[k];
    }
    #pragma unroll
    for (int o = 4; o; o >>= 1) acc += __shfl_down_sync(0xffffffffu, acc, o, 8);
    if (l8 == 0 && p < POOLN) ssim[p] = acc;
    __syncthreads();
    if (write_aux && tid < POOLN) out[OFF_SIM + (size_t)b * POOLN + tid] = ssim[tid];
    if (tid == 0) {
        bool used[POOLN];
        #pragma unroll
        for (int i = 0; i < POOLN; i++) used[i] = false;
        float rs = 0.f;
        for (int k = 0; k < TOPK; k++) {
            int best = 0;
            float bv = -3.4e38f;
            for (int pp = 0; pp < POOLN; pp++) {
                if (!used[pp] && ssim[pp] > bv) { bv = ssim[pp]; best = pp; }
            }
            used[best] = true;
            g_idx[b * TOPK + k] = best;
            if (write_aux) out[OFF_IDX + (size_t)b * TOPK + k] = (float)best;
            rs += bv;
        }
        g_rsum[b] = rs;
    }
}

// ---------------------------------------------------------------------------
// K3b: deterministic reduction of g_rsum -> out[OFF_RSIM].
// ---------------------------------------------------------------------------
__global__ __launch_bounds__(256) void reduce_rsim_kernel(float* __restrict__ out) {
    int tid = threadIdx.x;
    float v = g_rsum[tid] + g_rsum[tid + 256] + g_rsum[tid + 512] + g_rsum[tid + 768];
    __shared__ float sh[8];
    #pragma unroll
    for (int o = 16; o; o >>= 1) v += __shfl_down_sync(0xffffffffu, v, o);
    if ((tid & 31) == 0) sh[tid >> 5] = v;
    __syncthreads();
    if (tid < 32) {
        float w = (tid < 8) ? sh[tid] : 0.f;
        #pragma unroll
        for (int o = 4; o; o >>= 1) w += __shfl_down_sync(0xffffffffu, w, o);
        if (tid == 0) out[OFF_RSIM] = w * (1.f / BDIM);
    }
}

// ---------------------------------------------------------------------------
// K4: fully fused mlp_1 (token mixing).  grid = (12 d-chunks, B), block=256.
// ---------------------------------------------------------------------------
__global__ __launch_bounds__(256) void mlp1_fused_kernel(
    const float* __restrict__ x_embed, const float* __restrict__ prompt,
    const float* __restrict__ w1a, const float* __restrict__ b1a,
    const float* __restrict__ g1a, const float* __restrict__ be1a,
    const float* __restrict__ w1b, const float* __restrict__ b1b,
    const float* __restrict__ g1b, const float* __restrict__ be1b)
{
    extern __shared__ float sm[];
    float* sW1a  = sm;              // 68*64 = 4352
    float* sW1b  = sm + 4352;       // 64*64 = 4096
    float* sA    = sm + 8448;       // 68*64 = 4352  (later reused as H2, stride 65)
    float* sH    = sm + 12800;      // 64*65 = 4160
    float* sMean = sm + 16960;      // 64
    float* sRstd = sm + 17024;      // 64  -> total 17088 floats

    int b  = blockIdx.y;
    int d0 = blockIdx.x * 64;
    int tid = threadIdx.x;

    for (int i = tid; i < SEQL * 64; i += 256) sW1a[i] = w1a[i];
    for (int i = tid; i < 64 * 64;  i += 256) sW1b[i] = w1b[i];
    for (int i = tid; i < SEQL * 64; i += 256) {
        int s = i >> 6, dd = i & 63;
        float v;
        if (s < TOPK)
            v = prompt[(size_t)g_idx[b * TOPK + s] * DDIM + d0 + dd];
        else
            v = x_embed[((size_t)b * SDIM + (s - TOPK)) * DDIM + d0 + dd];
        sA[i] = v;
    }
    __syncthreads();

    int tx = tid & 15;
    int ty = tid >> 4;
    float acc[4][4];
    #pragma unroll
    for (int i = 0; i < 4; i++)
        #pragma unroll
        for (int j = 0; j < 4; j++) acc[i][j] = 0.f;

    #pragma unroll 4
    for (int s = 0; s < SEQL; s++) {
        float a[4], w[4];
        #pragma unroll
        for (int i = 0; i < 4; i++) a[i] = sA[s * 64 + ty * 4 + i];
        #pragma unroll
        for (int j = 0; j < 4; j++) w[j] = sW1a[s * 64 + tx * 4 + j];
        #pragma unroll
        for (int i = 0; i < 4; i++)
            #pragma unroll
            for (int j = 0; j < 4; j++) acc[i][j] += a[i] * w[j];
    }
    #pragma unroll
    for (int i = 0; i < 4; i++) {
        int r = ty * 4 + i;
        #pragma unroll
        for (int j = 0; j < 4; j++) {
            int c = tx * 4 + j;
            sH[r * 65 + c] = fmaxf(acc[i][j] + b1a[c], 0.f);
        }
    }
    __syncthreads();
    if (tid < 64) {
        float s = 0.f, sq = 0.f;
        #pragma unroll 8
        for (int c = 0; c < 64; c++) { float v = sH[tid * 65 + c]; s += v; sq += v * v; }
        float m = s * (1.f / 64.f);
        float var = sq * (1.f / 64.f) - m * m;
        sMean[tid] = m;
        sRstd[tid] = rsqrtf(fmaxf(var, 0.f) + 1e-5f);
    }
    __syncthreads();
    for (int i = tid; i < 4096; i += 256) {
        int r = i >> 6, c = i & 63;
        sH[r * 65 + c] = (sH[r * 65 + c] - sMean[r]) * sRstd[r] * g1a[c] + be1a[c];
    }
    __syncthreads();

    #pragma unroll
    for (int i = 0; i < 4; i++)
        #pragma unroll
        for (int j = 0; j < 4; j++) acc[i][j] = 0.f;
    #pragma unroll 8
    for (int k = 0; k < 64; k++) {
        float a[4], w[4];
        #pragma unroll
        for (int i = 0; i < 4; i++) a[i] = sH[(ty * 4 + i) * 65 + k];
        #pragma unroll
        for (int j = 0; j < 4; j++) w[j] = sW1b[k * 64 + tx * 4 + j];
        #pragma unroll
        for (int i = 0; i < 4; i++)
            #pragma unroll
            for (int j = 0; j < 4; j++) acc[i][j] += a[i] * w[j];
    }
    #pragma unroll
    for (int i = 0; i < 4; i++) {
        int r = ty * 4 + i;
        #pragma unroll
        for (int j = 0; j < 4; j++) {
            int c = tx * 4 + j;
            sA[r * 65 + c] = fmaxf(acc[i][j] + b1b[c], 0.f);
        }
    }
    __syncthreads();
    if (tid < 64) {
        float s = 0.f, sq = 0.f;
        #pragma unroll 8
        for (int c = 0; c < 64; c++) { float v = sA[tid * 65 + c]; s += v; sq += v * v; }
        float m = s * (1.f / 64.f);
        float var = sq * (1.f / 64.f) - m * m;
        sMean[tid] = m;
        sRstd[tid] = rsqrtf(fmaxf(var, 0.f) + 1e-5f);
    }
    __syncthreads();
    for (int i = tid; i < 4096; i += 256) {
        int r = i >> 6, c = i & 63;
        sA[r * 65 + c] = (sA[r * 65 + c] - sMean[r]) * sRstd[r] * g1b[c] + be1b[c];
    }
    __syncthreads();
    for (int i = tid; i < 4096; i += 256) {
        int c = i >> 6, dd = i & 63;
        g_bufA[((size_t)b * CTOK + c) * DDIM + d0 + dd] = sA[dd * 65 + c];
    }
}

// ---------------------------------------------------------------------------
// K5/K7: tf32 tensor-core GEMM  C = relu(A @ W + bias).
// A: MxK row-major, W: KxN row-major, C: MxN row-major.
// Block tile 128x128x16, 8 warps (each 64x32), m16n8k8 tf32 mma,
// double-buffered smem, +8 padding => conflict-free fragment loads.
// M % 128 == 0, N % 128 == 0, K % 16 == 0 assumed.
// ---------------------------------------------------------------------------
#define TBM 128
#define TBN 128
#define TBK 16

__global__ __launch_bounds__(256) void gemm_tf32_bias_relu(
    const float* __restrict__ A, const float* __restrict__ W,
    const float* __restrict__ bias, float* __restrict__ C,
    int M, int N, int K)
{
    __shared__ uint32_t As[2][TBK][TBM + 8];
    __shared__ uint32_t Bs[2][TBK][TBN + 8];

    const int tid  = threadIdx.x;
    const int lane = tid & 31;
    const int warp = tid >> 5;
    const int tg   = lane & 3;      // thread-in-group
    const int g    = lane >> 2;     // group id (0..7)

    const int warpM = (warp & 1) * 64;   // 2 warps along M
    const int warpN = (warp >> 1) * 32;  // 4 warps along N

    const int bx = blockIdx.x;  // N tile
    const int by = blockIdx.y;  // M tile

    const float* Ag = A + (size_t)by * TBM * K;
    const float* Wg = W + (size_t)bx * TBN;

    // A loader: 512 float4 per tile (128 rows x 4 f4). thread covers idx=tid, tid+256.
    const int arow0 = tid >> 2;          // 0..63
    const int ac4   = tid & 3;           // 0..3  (k-quad)
    // B loader: 512 float4 per tile (16 rows x 32 f4).
    const int brow0 = tid >> 5;          // 0..7
    const int bc4   = tid & 31;          // 0..31

    float acc[4][4][4];
    #pragma unroll
    for (int mi = 0; mi < 4; mi++)
        #pragma unroll
        for (int ni = 0; ni < 4; ni++)
            #pragma unroll
            for (int e = 0; e < 4; e++) acc[mi][ni][e] = 0.f;

    // ---- preload tile 0 into buffer 0 ----
    {
        float4 a0 = *(const float4*)(Ag + (size_t)arow0 * K + ac4 * 4);
        float4 a1 = *(const float4*)(Ag + (size_t)(arow0 + 64) * K + ac4 * 4);
        float4 b0 = *(const float4*)(Wg + (size_t)brow0 * N + bc4 * 4);
        float4 b1 = *(const float4*)(Wg + (size_t)(brow0 + 8) * N + bc4 * 4);
        As[0][ac4 * 4 + 0][arow0] = f2tf32(a0.x);
        As[0][ac4 * 4 + 1][arow0] = f2tf32(a0.y);
        As[0][ac4 * 4 + 2][arow0] = f2tf32(a0.z);
        As[0][ac4 * 4 + 3][arow0] = f2tf32(a0.w);
        As[0][ac4 * 4 + 0][arow0 + 64] = f2tf32(a1.x);
        As[0][ac4 * 4 + 1][arow0 + 64] = f2tf32(a1.y);
        As[0][ac4 * 4 + 2][arow0 + 64] = f2tf32(a1.z);
        As[0][ac4 * 4 + 3][arow0 + 64] = f2tf32(a1.w);
        uint4 u0 = { f2tf32(b0.x), f2tf32(b0.y), f2tf32(b0.z), f2tf32(b0.w) };
        uint4 u1 = { f2tf32(b1.x), f2tf32(b1.y), f2tf32(b1.z), f2tf32(b1.w) };
        *(uint4*)&Bs[0][brow0][bc4 * 4]     = u0;
        *(uint4*)&Bs[0][brow0 + 8][bc4 * 4] = u1;
    }
    __syncthreads();

    const int nTiles = K / TBK;
    for (int t = 0; t < nTiles; t++) {
        const int cur = t & 1;
        const int nxt = cur ^ 1;

        float4 pa0, pa1, pb0, pb1;
        const bool have_next = (t + 1 < nTiles);
        if (have_next) {
            int k0 = (t + 1) * TBK;
            pa0 = *(const float4*)(Ag + (size_t)arow0 * K + k0 + ac4 * 4);
            pa1 = *(const float4*)(Ag + (size_t)(arow0 + 64) * K + k0 + ac4 * 4);
            pb0 = *(const float4*)(Wg + (size_t)(k0 + brow0) * N + bc4 * 4);
            pb1 = *(const float4*)(Wg + (size_t)(k0 + brow0 + 8) * N + bc4 * 4);
        }

        // ---- compute on cur ----
        #pragma unroll
        for (int kk = 0; kk < TBK; kk += 8) {
            uint32_t af[4][4];
            uint32_t bf[4][2];
            #pragma unroll
            for (int mi = 0; mi < 4; mi++) {
                int m = warpM + mi * 16 + g;
                af[mi][0] = As[cur][kk + tg][m];
                af[mi][1] = As[cur][kk + tg][m + 8];
                af[mi][2] = As[cur][kk + tg + 4][m];
                af[mi][3] = As[cur][kk + tg + 4][m + 8];
            }
            #pragma unroll
            for (int ni = 0; ni < 4; ni++) {
                int n = warpN + ni * 8 + g;
                bf[ni][0] = Bs[cur][kk + tg][n];
                bf[ni][1] = Bs[cur][kk + tg + 4][n];
            }
            #pragma unroll
            for (int mi = 0; mi < 4; mi++)
                #pragma unroll
                for (int ni = 0; ni < 4; ni++)
                    mma_tf32(acc[mi][ni], af[mi][0], af[mi][1], af[mi][2], af[mi][3],
                             bf[ni][0], bf[ni][1]);
        }

        if (have_next) {
            __syncthreads();
            As[nxt][ac4 * 4 + 0][arow0] = f2tf32(pa0.x);
            As[nxt][ac4 * 4 + 1][arow0] = f2tf32(pa0.y);
            As[nxt][ac4 * 4 + 2][arow0] = f2tf32(pa0.z);
            As[nxt][ac4 * 4 + 3][arow0] = f2tf32(pa0.w);
            As[nxt][ac4 * 4 + 0][arow0 + 64] = f2tf32(pa1.x);
            As[nxt][ac4 * 4 + 1][arow0 + 64] = f2tf32(pa1.y);
            As[nxt][ac4 * 4 + 2][arow0 + 64] = f2tf32(pa1.z);
            As[nxt][ac4 * 4 + 3][arow0 + 64] = f2tf32(pa1.w);
            uint4 u0 = { f2tf32(pb0.x), f2tf32(pb0.y), f2tf32(pb0.z), f2tf32(pb0.w) };
            uint4 u1 = { f2tf32(pb1.x), f2tf32(pb1.y), f2tf32(pb1.z), f2tf32(pb1.w) };
            *(uint4*)&Bs[nxt][brow0][bc4 * 4]     = u0;
            *(uint4*)&Bs[nxt][brow0 + 8][bc4 * 4] = u1;
            __syncthreads();
        }
    }

    // ---- epilogue: bias + relu, float2 stores ----
    const int colBlock = bx * TBN;
    #pragma unroll
    for (int mi = 0; mi < 4; mi++) {
        size_t row0 = (size_t)by * TBM + warpM + mi * 16 + g;
        #pragma unroll
        for (int ni = 0; ni < 4; ni++) {
            int col = colBlock + warpN + ni * 8 + tg * 2;
            float bia0 = bias[col], bia1 = bias[col + 1];
            float2 v0, v1;
            v0.x = fmaxf(acc[mi][ni][0] + bia0, 0.f);
            v0.y = fmaxf(acc[mi][ni][1] + bia1, 0.f);
            v1.x = fmaxf(acc[mi][ni][2] + bia0, 0.f);
            v1.y = fmaxf(acc[mi][ni][3] + bia1, 0.f);
            *(float2*)&C[row0 * N + col]       = v0;
            *(float2*)&C[(row0 + 8) * N + col] = v1;
        }
    }
}

// ---------------------------------------------------------------------------
// K6/K8: per-row LayerNorm over 768.  grid = B*CT rows, block=256.
// ---------------------------------------------------------------------------
__global__ __launch_bounds__(256) void ln_rows_kernel(
    const float* __restrict__ in, float* __restrict__ out,
    const float* __restrict__ g, const float* __restrict__ be)
{
    size_t row = blockIdx.x;
    int tid = threadIdx.x;
    const float* p = in + row * DDIM;
    float* q = out + row * DDIM;
    float v0 = p[tid], v1 = p[tid + 256], v2 = p[tid + 512];
    float s = v0 + v1 + v2;
    float sq = v0 * v0 + v1 * v1 + v2 * v2;
    __shared__ float sh[16];
    #pragma unroll
    for (int o = 16; o; o >>= 1) {
        s  += __shfl_down_sync(0xffffffffu, s, o);
        sq += __shfl_down_sync(0xffffffffu, sq, o);
    }
    if ((tid & 31) == 0) { sh[tid >> 5] = s; sh[8 + (tid >> 5)] = sq; }
    __syncthreads();
    if (tid < 32) {
        float a = (tid < 8) ? sh[tid] : 0.f;
        float c = (tid < 8) ? sh[8 + tid] : 0.f;
        #pragma unroll
        for (int o = 4; o; o >>= 1) {
            a += __shfl_down_sync(0xffffffffu, a, o);
            c += __shfl_down_sync(0xffffffffu, c, o);
        }
        if (tid == 0) { sh[0] = a; sh[1] = c; }
    }
    __syncthreads();
    float mean = sh[0] * (1.f / DDIM);
    float var  = sh[1] * (1.f / DDIM) - mean * mean;
    float rstd = rsqrtf(fmaxf(var, 0.f) + 1e-5f);
    q[tid]       = (v0 - mean) * rstd * g[tid]       + be[tid];
    q[tid + 256] = (v1 - mean) * rstd * g[tid + 256] + be[tid + 256];
    q[tid + 512] = (v2 - mean) * rstd * g[tid + 512] + be[tid + 512];
}

// ---------------------------------------------------------------------------
// Launch
// ---------------------------------------------------------------------------
extern "C" void kernel_launch(void* const* d_in, const int* in_sizes, int n_in,
                              void* d_out, int out_size)
{
    const float* x_embed = (const float*)d_in[0];
    const float* prompt  = (const float*)d_in[1];
    const float* w1a  = (const float*)d_in[2];
    const float* b1a  = (const float*)d_in[3];
    const float* g1a  = (const float*)d_in[4];
    const float* be1a = (const float*)d_in[5];
    const float* w1b  = (const float*)d_in[6];
    const float* b1b  = (const float*)d_in[7];
    const float* g1b  = (const float*)d_in[8];
    const float* be1b = (const float*)d_in[9];
    const float* w2a  = (const float*)d_in[10];
    const float* b2a  = (const float*)d_in[11];
    const float* g2a  = (const float*)d_in[12];
    const float* be2a = (const float*)d_in[13];
    const float* w2b  = (const float*)d_in[14];
    const float* b2b  = (const float*)d_in[15];
    const float* g2b  = (const float*)d_in[16];
    const float* be2b = (const float*)d_in[17];
    float* out = (float*)d_out;

    int write_aux = (out_size >= OUT_TOTAL) ? 1 : 0;

    float *bufA = nullptr, *bufB = nullptr;
    cudaGetSymbolAddress((void**)&bufA, g_bufA);
    cudaGetSymbolAddress((void**)&bufB, g_bufB);

    // prompt selection pipeline
    pnorm_kernel<<<POOLN, 256>>>(prompt);
    xmean_norm_kernel<<<BDIM, 256>>>(x_embed);
    sim_topk_kernel<<<BDIM, 256>>>(out, write_aux);
    if (write_aux) reduce_rsim_kernel<<<1, 256>>>(out);

    // fused mlp_1 (token mixing): writes z_t into bufA
    int mlp1_smem = 17088 * (int)sizeof(float);
    cudaFuncSetAttribute(mlp1_fused_kernel,
                         cudaFuncAttributeMaxDynamicSharedMemorySize, mlp1_smem);
    mlp1_fused_kernel<<<dim3(DDIM / 64, BDIM), 256, mlp1_smem>>>(
        x_embed, prompt, w1a, b1a, g1a, be1a, w1b, b1b, g1b, be1b);

    // mlp_2 (channel mixing): two tf32 GEMM + LN stages
    dim3 ggrid(DDIM / TBN, (BDIM * CTOK) / TBM);   // (6, 512)
    gemm_tf32_bias_relu<<<ggrid, 256>>>(bufA, w2a, b2a, bufB,
                                        BDIM * CTOK, DDIM, DDIM);
    ln_rows_kernel<<<BDIM * CTOK, 256>>>(bufB, bufA, g2a, be2a);
    gemm_tf32_bias_relu<<<ggrid, 256>>>(bufA, w2b, b2b, bufB,
                                        BDIM * CTOK, DDIM, DDIM);
    ln_rows_kernel<<<BDIM * CTOK, 256>>>(bufB, out, g2b, be2b);
}